// round 17
// baseline (speedup 1.0000x reference)
#include <cuda_runtime.h>
#include <cuda_bf16.h>

#define H    32
#define DX   16
#define HQ   16
#define NMAX 50048

typedef unsigned long long u64;
typedef unsigned int u32;
typedef __nv_bfloat162 bf2;

__device__ __align__(16) float g_x[NMAX * DX];
__device__ __align__(16) u32 g_xb[NMAX * 8];     // bf16 mirror of x (16 vals)
__device__ __align__(16) float4 g_pos4[NMAX];    // padded positions
__device__ __align__(16) float g_h[NMAX * H];
__device__ __align__(16) u32 g_A[NMAX * HQ];
__device__ __align__(16) u32 g_B[NMAX * HQ];
__device__ __align__(16) float g_magg[NMAX * H];
__device__ __align__(16) float g_tagg[NMAX * DX];
__device__ float g_cnt[NMAX];
__device__ int g_dummy;

__device__ __forceinline__ float silu_f(float v) {
    return v * (1.0f / (1.0f + __expf(-v)));
}
__device__ __forceinline__ u32 b2u(bf2 v) { return *reinterpret_cast<u32*>(&v); }
__device__ __forceinline__ bf2 u2b(u32 v) { return *reinterpret_cast<bf2*>(&v); }

__device__ __forceinline__ bf2 silu_b(bf2 v) {
    bf2 h = __hmul2(v, __float2bfloat162_rn(0.5f));
    u32 tu;
    u32 hu = b2u(h);
    asm("tanh.approx.bf16x2 %0, %1;" : "=r"(tu) : "r"(hu));
    return __hmul2(h, __hadd2(u2b(tu), __float2bfloat162_rn(1.0f)));
}

// pack two f32 into bf16x2 (lo first)
__device__ __forceinline__ u32 packf(float lo, float hi) {
    u32 r; asm("cvt.rn.bf16x2.f32 %0, %1, %2;" : "=r"(r) : "f"(hi), "f"(lo)); return r;
}

__device__ __forceinline__ void mma16816(float& c0, float& c1, float& c2, float& c3,
                                         u32 a0, u32 a1, u32 a2, u32 a3, u32 b0, u32 b1) {
    asm("mma.sync.aligned.m16n8k16.row.col.f32.bf16.bf16.f32 "
        "{%0,%1,%2,%3},{%4,%5,%6,%7},{%8,%9},{%0,%1,%2,%3};"
        : "+f"(c0), "+f"(c1), "+f"(c2), "+f"(c3)
        : "r"(a0), "r"(a1), "r"(a2), "r"(a3), "r"(b0), "r"(b1));
}

__device__ __forceinline__ void red_add_v4(float* a, float x, float y, float z, float w) {
    asm volatile("red.global.add.v4.f32 [%0], {%1,%2,%3,%4};"
                 :: "l"(a), "f"(x), "f"(y), "f"(z), "f"(w) : "memory");
}

// ---------------------------------------------------------------------------
__global__ __launch_bounds__(128, 4) void init_kernel(
    const float* __restrict__ attrs, const float* __restrict__ pos,
    const float* __restrict__ projW, const float* __restrict__ embW,
    const float* __restrict__ embB, const float* __restrict__ eW1,
    const float* __restrict__ eb1, int n)
{
    __shared__ __align__(16) float sWa[H][H];
    __shared__ __align__(16) float sWb[H][H];
    for (int idx = threadIdx.x; idx < H * H; idx += 128) {
        int j = idx >> 5, k = idx & 31;
        sWa[k][j] = eW1[j * 68 + k];
        sWb[k][j] = eW1[j * 68 + 32 + k];
    }
    __syncthreads();
    int i = blockIdx.x * 128 + threadIdx.x;
    if (i >= n) return;

    float p0 = pos[i*3], p1 = pos[i*3+1], p2 = pos[i*3+2];
    g_pos4[i] = make_float4(p0, p1, p2, 0.0f);

    float xv[DX];
#pragma unroll
    for (int j = 0; j < DX; j++)
        xv[j] = projW[j*3]*p0 + projW[j*3+1]*p1 + projW[j*3+2]*p2;
    float4* xo = (float4*)&g_x[i * DX];
#pragma unroll
    for (int q = 0; q < 4; q++)
        xo[q] = make_float4(xv[4*q], xv[4*q+1], xv[4*q+2], xv[4*q+3]);
    uint4* xb = (uint4*)&g_xb[i * 8];
#pragma unroll
    for (int q = 0; q < 2; q++)
        xb[q] = make_uint4(packf(xv[8*q],   xv[8*q+1]), packf(xv[8*q+2], xv[8*q+3]),
                           packf(xv[8*q+4], xv[8*q+5]), packf(xv[8*q+6], xv[8*q+7]));

    float a0 = attrs[i*3], a1 = attrs[i*3+1], a2 = attrs[i*3+2];
    float hv[H];
#pragma unroll
    for (int j = 0; j < H; j++)
        hv[j] = embW[j*3]*a0 + embW[j*3+1]*a1 + embW[j*3+2]*a2 + embB[j];
    float4* ho = (float4*)&g_h[i * H];
#pragma unroll
    for (int q = 0; q < 8; q++)
        ho[q] = make_float4(hv[4*q], hv[4*q+1], hv[4*q+2], hv[4*q+3]);

    float Av[H], Bv[H];
#pragma unroll
    for (int j = 0; j < H; j++) { Av[j] = eb1[j]; Bv[j] = 0.0f; }
#pragma unroll
    for (int k = 0; k < H; k++) {
        float hk = hv[k];
        const float4* wa = (const float4*)&sWa[k][0];
        const float4* wb = (const float4*)&sWb[k][0];
#pragma unroll
        for (int q = 0; q < 8; q++) {
            float4 a = wa[q], b = wb[q];
            Av[4*q] += a.x*hk; Av[4*q+1] += a.y*hk; Av[4*q+2] += a.z*hk; Av[4*q+3] += a.w*hk;
            Bv[4*q] += b.x*hk; Bv[4*q+1] += b.y*hk; Bv[4*q+2] += b.z*hk; Bv[4*q+3] += b.w*hk;
        }
    }
    u32 pa[HQ], pb[HQ];
#pragma unroll
    for (int jq = 0; jq < HQ; jq++) {
        pa[jq] = packf(Av[2*jq], Av[2*jq+1]);
        pb[jq] = packf(Bv[2*jq], Bv[2*jq+1]);
    }
    uint4* Ao = (uint4*)&g_A[i * HQ];
    uint4* Bo = (uint4*)&g_B[i * HQ];
#pragma unroll
    for (int q = 0; q < 4; q++) {
        Ao[q] = make_uint4(pa[4*q], pa[4*q+1], pa[4*q+2], pa[4*q+3]);
        Bo[q] = make_uint4(pb[4*q], pb[4*q+1], pb[4*q+2], pb[4*q+3]);
    }

    const float4 z4 = make_float4(0.f, 0.f, 0.f, 0.f);
    float4* mz = (float4*)&g_magg[i * H];
    float4* tz = (float4*)&g_tagg[i * DX];
#pragma unroll
    for (int q = 0; q < 8; q++) mz[q] = z4;
#pragma unroll
    for (int q = 0; q < 4; q++) tz[q] = z4;
    g_cnt[i] = 0.0f;
}

__global__ void count_kernel(const int* __restrict__ ei, int E)
{
    int e = blockIdx.x * blockDim.x + threadIdx.x;
    if (e < E) atomicAdd(&g_cnt[ei[e]], 1.0f);
}

__global__ void nop_kernel() { if (blockIdx.x == 1u << 30) g_dummy = 1; }

// ---------------------------------------------------------------------------
// edge kernel: warp = 32 edges; mma.sync bf16 with register weights.
// R17: lane-paired red.v4 message scatters (halved RED lane-ops).
// ---------------------------------------------------------------------------
#define EBLK 128
#define SSTR 80

__global__ __launch_bounds__(EBLK) void edge_kernel(
    const int* __restrict__ ei, int E,
    const float* __restrict__ W1,   // [32][68], cols 64..67 = geo coeffs
    const float* __restrict__ W2,   // [32][32]
    const float* __restrict__ b2,
    const float* __restrict__ cW1,  // [32][32]
    const float* __restrict__ cb1,
    const float* __restrict__ cW2)  // [32]
{
    __shared__ __align__(16) unsigned char sS[4][32 * SSTR];
    __shared__ __align__(8)  u32 sG[4][32 * 2];
    __shared__ int sRow[4][32];

    int tid = threadIdx.x, wid = tid >> 5, lane = tid & 31;
    int g = lane >> 2, t = lane & 3;

    // one-time register weight fragments
    u32 WB[2][4][2], CB[2][4][2], GB[4];
    float B2c0[4], B2c1[4], CB1c0[4], CB1c1[4];
    u32 CW2p[4];
#pragma unroll
    for (int nt = 0; nt < 4; nt++) {
        int j = 8 * nt + g;
#pragma unroll
        for (int kt = 0; kt < 2; kt++) {
            int k0 = 16 * kt + 2 * t;
            WB[kt][nt][0] = packf(W2[j*H + k0],     W2[j*H + k0 + 1]);
            WB[kt][nt][1] = packf(W2[j*H + k0 + 8], W2[j*H + k0 + 9]);
            CB[kt][nt][0] = packf(cW1[j*H + k0],     cW1[j*H + k0 + 1]);
            CB[kt][nt][1] = packf(cW1[j*H + k0 + 8], cW1[j*H + k0 + 9]);
        }
        float glo = 0.f, ghi = 0.f;
        if (t == 0) { glo = W1[j*68 + 64]; ghi = W1[j*68 + 65]; }
        else if (t == 1) { glo = W1[j*68 + 66]; ghi = W1[j*68 + 67]; }
        GB[nt] = packf(glo, ghi);

        int jc = 8 * nt + 2 * t;
        B2c0[nt]  = b2[jc];   B2c1[nt]  = b2[jc + 1];
        CB1c0[nt] = cb1[jc];  CB1c1[nt] = cb1[jc + 1];
        CW2p[nt]  = packf(cW2[jc], cW2[jc + 1]);
    }

    unsigned char* mS = &sS[wid][0];
    u32* mG = &sG[wid][0];
    int* mR = &sRow[wid][0];

    int warps_total = gridDim.x * (EBLK / 32);
    int wgl = blockIdx.x * (EBLK / 32) + wid;

    for (int base = wgl * 32; base < E; base += warps_total * 32) {
        int e = base + lane;
        bool vme = (e < E);
        int ec = vme ? e : (E - 1);
        int row = ei[ec], col = ei[E + ec];
        mR[lane] = row;

        float4 pr = g_pos4[row];
        float4 pc = g_pos4[col];
        float ea0 = pr.x - pc.x;
        float ea1 = pr.y - pc.y;
        float ea2 = pr.z - pc.z;

        bf2 cd[8];
        float radial = 0.0f;
        {
            const uint4* xr = (const uint4*)&g_xb[row * 8];
            const uint4* xc = (const uint4*)&g_xb[col * 8];
#pragma unroll
            for (int q = 0; q < 2; q++) {
                uint4 a4 = xr[q], b4 = xc[q];
                const u32* ap = (const u32*)&a4;
                const u32* bp = (const u32*)&b4;
#pragma unroll
                for (int r = 0; r < 4; r++) {
                    float2 af = __bfloat1622float2(u2b(ap[r]));
                    float2 bf = __bfloat1622float2(u2b(bp[r]));
                    float d0 = af.x - bf.x, d1 = af.y - bf.y;
                    cd[4*q + r] = u2b(packf(d0, d1));
                    radial += d0*d0 + d1*d1;
                }
            }
        }

        // stage geo and A[row]+B[col] sums
        mG[lane*2 + 0] = packf(radial, ea0);
        mG[lane*2 + 1] = packf(ea1, ea2);
        {
            const uint4* Ar = (const uint4*)&g_A[row * HQ];
            const uint4* Bc = (const uint4*)&g_B[col * HQ];
            uint4* dst = (uint4*)&mS[lane * SSTR];
#pragma unroll
            for (int q = 0; q < 4; q++) {
                uint4 a4 = Ar[q], b4 = Bc[q];
                uint4 o;
                o.x = b2u(__hadd2(u2b(a4.x), u2b(b4.x)));
                o.y = b2u(__hadd2(u2b(a4.y), u2b(b4.y)));
                o.z = b2u(__hadd2(u2b(a4.z), u2b(b4.z)));
                o.w = b2u(__hadd2(u2b(a4.w), u2b(b4.w)));
                dst[q] = o;
            }
        }
        __syncwarp();

        // layer 1
        bf2 msm[2][4][2];
#pragma unroll
        for (int mt = 0; mt < 2; mt++) {
            u32 ga0 = 0, ga1 = 0;
            if (t < 2) {
                ga0 = mG[(mt*16 + g) * 2 + t];
                ga1 = mG[(mt*16 + g + 8) * 2 + t];
            }
#pragma unroll
            for (int nt = 0; nt < 4; nt++) {
                u32 s0 = *(const u32*)&mS[(mt*16 + g) * SSTR + 16*nt + 4*t];
                u32 s1 = *(const u32*)&mS[(mt*16 + g + 8) * SSTR + 16*nt + 4*t];
                float2 f0 = __bfloat1622float2(u2b(s0));
                float2 f1 = __bfloat1622float2(u2b(s1));
                float c0 = f0.x, c1 = f0.y, c2 = f1.x, c3 = f1.y;
                mma16816(c0, c1, c2, c3, ga0, ga1, 0u, 0u, GB[nt], 0u);
                msm[mt][nt][0] = silu_b(u2b(packf(c0, c1)));
                msm[mt][nt][1] = silu_b(u2b(packf(c2, c3)));
            }
        }

        // layer 2
        bf2 out2[2][4][2];
#pragma unroll
        for (int mt = 0; mt < 2; mt++) {
            u32 A0[2][4];
#pragma unroll
            for (int kt = 0; kt < 2; kt++) {
                A0[kt][0] = b2u(msm[mt][2*kt][0]);
                A0[kt][1] = b2u(msm[mt][2*kt][1]);
                A0[kt][2] = b2u(msm[mt][2*kt+1][0]);
                A0[kt][3] = b2u(msm[mt][2*kt+1][1]);
            }
#pragma unroll
            for (int nt = 0; nt < 4; nt++) {
                float c0 = B2c0[nt], c1 = B2c1[nt], c2 = B2c0[nt], c3 = B2c1[nt];
                mma16816(c0, c1, c2, c3, A0[0][0], A0[0][1], A0[0][2], A0[0][3],
                         WB[0][nt][0], WB[0][nt][1]);
                mma16816(c0, c1, c2, c3, A0[1][0], A0[1][1], A0[1][2], A0[1][3],
                         WB[1][nt][0], WB[1][nt][1]);
                out2[mt][nt][0] = silu_b(u2b(packf(c0, c1)));
                out2[mt][nt][1] = silu_b(u2b(packf(c2, c3)));
            }
        }

        // coord head
        float pl[4];
#pragma unroll
        for (int mt = 0; mt < 2; mt++) {
            u32 A0[2][4];
#pragma unroll
            for (int kt = 0; kt < 2; kt++) {
                A0[kt][0] = b2u(out2[mt][2*kt][0]);
                A0[kt][1] = b2u(out2[mt][2*kt][1]);
                A0[kt][2] = b2u(out2[mt][2*kt+1][0]);
                A0[kt][3] = b2u(out2[mt][2*kt+1][1]);
            }
            float slo = 0.f, shi = 0.f;
#pragma unroll
            for (int nt = 0; nt < 4; nt++) {
                float c0 = CB1c0[nt], c1 = CB1c1[nt], c2 = CB1c0[nt], c3 = CB1c1[nt];
                mma16816(c0, c1, c2, c3, A0[0][0], A0[0][1], A0[0][2], A0[0][3],
                         CB[0][nt][0], CB[0][nt][1]);
                mma16816(c0, c1, c2, c3, A0[1][0], A0[1][1], A0[1][2], A0[1][3],
                         CB[1][nt][0], CB[1][nt][1]);
                bf2 p0 = silu_b(u2b(packf(c0, c1)));
                bf2 p1 = silu_b(u2b(packf(c2, c3)));
                float2 q0 = __bfloat1622float2(__hmul2(p0, u2b(CW2p[nt])));
                float2 q1 = __bfloat1622float2(__hmul2(p1, u2b(CW2p[nt])));
                slo += q0.x + q0.y;
                shi += q1.x + q1.y;
            }
            pl[2*mt]     = slo;
            pl[2*mt + 1] = shi;
        }
#pragma unroll
        for (int d = 1; d <= 2; d <<= 1) {
            pl[0] += __shfl_xor_sync(0xffffffffu, pl[0], d);
            pl[1] += __shfl_xor_sync(0xffffffffu, pl[1], d);
            pl[2] += __shfl_xor_sync(0xffffffffu, pl[2], d);
            pl[3] += __shfl_xor_sync(0xffffffffu, pl[3], d);
        }
        int src = 4 * (lane & 7);
        float r0 = __shfl_sync(0xffffffffu, pl[0], src);
        float r1 = __shfl_sync(0xffffffffu, pl[1], src);
        float r2 = __shfl_sync(0xffffffffu, pl[2], src);
        float r3 = __shfl_sync(0xffffffffu, pl[3], src);
        int sel = lane >> 3;
        float cm = (sel == 0) ? r0 : (sel == 1) ? r1 : (sel == 2) ? r2 : r3;

        // ---- scatters: lane-paired red.v4 for messages ---------------------
#pragma unroll
        for (int mt = 0; mt < 2; mt++) {
            int eA = base + mt*16 + g;
            bool vA = (eA < E), vB = (eA + 8 < E);
            int rA = mR[mt*16 + g];
            int rB = mR[mt*16 + g + 8];
#pragma unroll
            for (int nt = 0; nt < 4; nt++) {
                u32 pA = b2u(out2[mt][nt][0]);
                u32 pB = b2u(out2[mt][nt][1]);
                u32 qA = __shfl_xor_sync(0xffffffffu, pA, 1);
                u32 qB = __shfl_xor_sync(0xffffffffu, pB, 1);
                if ((t & 1) == 0) {
                    int j0 = 8*nt + 2*t;   // t in {0,2} -> j0 in {8nt, 8nt+4}, 16B aligned
                    float2 a0 = __bfloat1622float2(u2b(pA));
                    float2 a1 = __bfloat1622float2(u2b(qA));
                    if (vA) red_add_v4(&g_magg[rA*H + j0], a0.x, a0.y, a1.x, a1.y);
                    float2 b0 = __bfloat1622float2(u2b(pB));
                    float2 b1 = __bfloat1622float2(u2b(qB));
                    if (vB) red_add_v4(&g_magg[rB*H + j0], b0.x, b0.y, b1.x, b1.y);
                }
            }
        }
        if (vme) {
            float* tago = &g_tagg[row * DX];
#pragma unroll
            for (int q = 0; q < 4; q++) {
                float2 d0 = __bfloat1622float2(cd[2*q]);
                float2 d1 = __bfloat1622float2(cd[2*q+1]);
                red_add_v4(tago + 4*q, d0.x*cm, d0.y*cm, d1.x*cm, d1.y*cm);
            }
        }
        __syncwarp();
    }
}

// ---------------------------------------------------------------------------
#define NTPB 128

__global__ __launch_bounds__(NTPB, 4) void node_kernel(
    const float* __restrict__ nW1, const float* __restrict__ nb1,
    const float* __restrict__ nW2, const float* __restrict__ nb2,
    const float* __restrict__ eW1n, const float* __restrict__ eb1n,
    const float* __restrict__ linW, float* __restrict__ out, int n)
{
    __shared__ __align__(16) float sN1t[2 * H][H];
    __shared__ __align__(16) float sN2t[H][H];
    __shared__ __align__(16) float sEAt[H][H];
    __shared__ __align__(16) float sEBt[H][H];

    int i = blockIdx.x * NTPB + threadIdx.x;
    bool active = (i < n);

    float cnt = 0.f;
    float4 xr[4], tr[4], hr[8], mr[8];
    if (active) {
        cnt = g_cnt[i];
        const float4* xp = (const float4*)&g_x[i * DX];
        const float4* tp = (const float4*)&g_tagg[i * DX];
        const float4* hp = (const float4*)&g_h[i * H];
        const float4* mp = (const float4*)&g_magg[i * H];
#pragma unroll
        for (int q = 0; q < 4; q++) { xr[q] = xp[q]; tr[q] = tp[q]; }
#pragma unroll
        for (int q = 0; q < 8; q++) { hr[q] = hp[q]; mr[q] = mp[q]; }
    }

    for (int idx = threadIdx.x; idx < H * 2 * H; idx += NTPB) {
        int j = idx >> 6, k = idx & 63;
        sN1t[k][j] = nW1[idx];
    }
    for (int idx = threadIdx.x; idx < H * H; idx += NTPB) {
        int j = idx >> 5, k = idx & 31;
        sN2t[k][j] = nW2[idx];
        if (eW1n) {
            sEAt[k][j] = eW1n[j * 68 + k];
            sEBt[k][j] = eW1n[j * 68 + 32 + k];
        }
    }
    __syncthreads();

    if (!active) return;

    float inv = 1.0f / fmaxf(cnt, 1.0f);
    const float4 z4 = make_float4(0.f, 0.f, 0.f, 0.f);

    float xv[DX];
    float4* xp = (float4*)&g_x[i * DX];
    float4* tp = (float4*)&g_tagg[i * DX];
#pragma unroll
    for (int q = 0; q < 4; q++) {
        xv[4*q]   = xr[q].x + tr[q].x * inv;
        xv[4*q+1] = xr[q].y + tr[q].y * inv;
        xv[4*q+2] = xr[q].z + tr[q].z * inv;
        xv[4*q+3] = xr[q].w + tr[q].w * inv;
        xp[q] = make_float4(xv[4*q], xv[4*q+1], xv[4*q+2], xv[4*q+3]);
        tp[q] = z4;
    }
    uint4* xb = (uint4*)&g_xb[i * 8];
#pragma unroll
    for (int q = 0; q < 2; q++)
        xb[q] = make_uint4(packf(xv[8*q],   xv[8*q+1]), packf(xv[8*q+2], xv[8*q+3]),
                           packf(xv[8*q+4], xv[8*q+5]), packf(xv[8*q+6], xv[8*q+7]));

    float hv[H], mg[H];
    float4* mp = (float4*)&g_magg[i * H];
#pragma unroll
    for (int q = 0; q < 8; q++) {
        hv[4*q] = hr[q].x; hv[4*q+1] = hr[q].y; hv[4*q+2] = hr[q].z; hv[4*q+3] = hr[q].w;
        mg[4*q] = mr[q].x; mg[4*q+1] = mr[q].y; mg[4*q+2] = mr[q].z; mg[4*q+3] = mr[q].w;
        mp[q] = z4;
    }

    float u[H];
#pragma unroll
    for (int j = 0; j < H; j++) u[j] = nb1[j];
#pragma unroll
    for (int k = 0; k < H; k++) {
        float v = hv[k];
        const float4* w4 = (const float4*)&sN1t[k][0];
#pragma unroll
        for (int q = 0; q < 8; q++) {
            float4 w = w4[q];
            u[4*q] += w.x*v; u[4*q+1] += w.y*v; u[4*q+2] += w.z*v; u[4*q+3] += w.w*v;
        }
    }
#pragma unroll
    for (int k = 0; k < H; k++) {
        float v = mg[k];
        const float4* w4 = (const float4*)&sN1t[H + k][0];
#pragma unroll
        for (int q = 0; q < 8; q++) {
            float4 w = w4[q];
            u[4*q] += w.x*v; u[4*q+1] += w.y*v; u[4*q+2] += w.z*v; u[4*q+3] += w.w*v;
        }
    }
#pragma unroll
    for (int j = 0; j < H; j++) u[j] = silu_f(u[j]);

    float hn[H];
#pragma unroll
    for (int j = 0; j < H; j++) hn[j] = nb2[j];
#pragma unroll
    for (int k = 0; k < H; k++) {
        float v = u[k];
        const float4* w4 = (const float4*)&sN2t[k][0];
#pragma unroll
        for (int q = 0; q < 8; q++) {
            float4 w = w4[q];
            hn[4*q] += w.x*v; hn[4*q+1] += w.y*v; hn[4*q+2] += w.z*v; hn[4*q+3] += w.w*v;
        }
    }
#pragma unroll
    for (int j = 0; j < H; j++) hn[j] += hv[j];
    float4* hp = (float4*)&g_h[i * H];
#pragma unroll
    for (int q = 0; q < 8; q++)
        hp[q] = make_float4(hn[4*q], hn[4*q+1], hn[4*q+2], hn[4*q+3]);

    if (eW1n) {
        float Av[H], Bv[H];
#pragma unroll
        for (int j = 0; j < H; j++) { Av[j] = eb1n[j]; Bv[j] = 0.0f; }
#pragma unroll
        for (int k = 0; k < H; k++) {
            float v = hn[k];
            const float4* wa = (const float4*)&sEAt[k][0];
            const float4* wb = (const float4*)&sEBt[k][0];
#pragma unroll
            for (int q = 0; q < 8; q++) {
                float4 a = wa[q], b = wb[q];
                Av[4*q] += a.x*v; Av[4*q+1] += a.y*v; Av[4*q+2] += a.z*v; Av[4*q+3] += a.w*v;
                Bv[4*q] += b.x*v; Bv[4*q+1] += b.y*v; Bv[4*q+2] += b.z*v; Bv[4*q+3] += b.w*v;
            }
        }
        u32 pa[HQ], pb[HQ];
#pragma unroll
        for (int jq = 0; jq < HQ; jq++) {
            pa[jq] = packf(Av[2*jq], Av[2*jq+1]);
            pb[jq] = packf(Bv[2*jq], Bv[2*jq+1]);
        }
        uint4* Ao = (uint4*)&g_A[i * HQ];
        uint4* Bo = (uint4*)&g_B[i * HQ];
#pragma unroll
        for (int q = 0; q < 4; q++) {
            Ao[q] = make_uint4(pa[4*q], pa[4*q+1], pa[4*q+2], pa[4*q+3]);
            Bo[q] = make_uint4(pb[4*q], pb[4*q+1], pb[4*q+2], pb[4*q+3]);
        }
    }

    if (linW) {
#pragma unroll
        for (int c = 0; c < 3; c++) {
            float acc = 0.0f;
#pragma unroll
            for (int k = 0; k < DX; k++) acc += linW[c * DX + k] * xv[k];
            out[i * 3 + c] = acc;
        }
    }
}

extern "C" void kernel_launch(void* const* d_in, const int* in_sizes, int n_in,
                              void* d_out, int out_size)
{
    const float* node_attrs = (const float*)d_in[0];
    const float* positions  = (const float*)d_in[1];
    const int*   edge_index = (const int*)  d_in[2];
    const float* proj_W     = (const float*)d_in[3];
    const float* emb_in_W   = (const float*)d_in[4];
    const float* emb_in_b   = (const float*)d_in[5];
    const float* edge_W1    = (const float*)d_in[6];
    const float* edge_b1    = (const float*)d_in[7];
    const float* edge_W2    = (const float*)d_in[8];
    const float* edge_b2    = (const float*)d_in[9];
    const float* node_W1    = (const float*)d_in[10];
    const float* node_b1    = (const float*)d_in[11];
    const float* node_W2    = (const float*)d_in[12];
    const float* node_b2    = (const float*)d_in[13];
    const float* coord_W1   = (const float*)d_in[14];
    const float* coord_b1   = (const float*)d_in[15];
    const float* coord_W2   = (const float*)d_in[16];
    const float* lin_W      = (const float*)d_in[19];

    int n = in_sizes[0] / 3;
    int E = in_sizes[2] / 2;
    float* out = (float*)d_out;

    init_kernel<<<(n + 127) / 128, 128>>>(node_attrs, positions, proj_W,
                                          emb_in_W, emb_in_b, edge_W1, edge_b1, n);
    count_kernel<<<(E + 255) / 256, 256>>>(edge_index, E);
    nop_kernel<<<1, 32>>>();

    int eblocks = 444;
    int nblocks = (n + NTPB - 1) / NTPB;

    for (int l = 0; l < 2; l++) {
        edge_kernel<<<eblocks, EBLK>>>(
            edge_index, E,
            edge_W1 + l * H * 68,
            edge_W2 + l * H * H, edge_b2 + l * H,
            coord_W1 + l * H * H, coord_b1 + l * H,
            coord_W2 + l * H);
        node_kernel<<<nblocks, NTPB>>>(
            node_W1 + l * H * 2 * H, node_b1 + l * H,
            node_W2 + l * H * H,     node_b2 + l * H,
            (l == 0) ? edge_W1 + H * 68 : nullptr,
            (l == 0) ? edge_b1 + H      : nullptr,
            (l == 1) ? lin_W            : nullptr,
            out, n);
    }
}